// round 15
// baseline (speedup 1.0000x reference)
#include <cuda_runtime.h>
#include <cuda_bf16.h>
#include <cstdint>
#include <math.h>

#define Bn 32768
#define Gn 2048
#define Hn 512
#define An 8
#define PH 64
#define HH 32
#define KE 576      // 64 (hid) + 512 (h_prev)
#define NE 2048     // interleaved: col 4j+{0,1,2,3} = {r_sum, z_sum, i_n, h_n}

// ---------------- device scratch ----------------
__device__ __nv_bfloat16 g_WextT[(size_t)NE * KE];   // folded weight, [n][k] bf16
__device__ float g_bias[NE];                         // interleaved fp32
__device__ __nv_bfloat16 g_hid[(size_t)Bn * PH];     // gemm1 output, bf16
__device__ __nv_bfloat16 g_hprev_b[(size_t)Bn * Hn]; // bf16 copy of h_prev

__device__ __forceinline__ int colp(int C) { return 4 * (C & 511) + (C >> 9); }

__device__ __forceinline__ uint32_t packbf(float a, float b) {
    __nv_bfloat162 v = __float22bfloat162_rn(make_float2(a, b));
    return *(uint32_t*)&v;
}

// ---------------- mma ----------------
__device__ __forceinline__ void mma_tf32(float* d, const uint32_t* a, const uint32_t* b) {
    asm volatile(
        "mma.sync.aligned.m16n8k8.row.col.f32.tf32.tf32.f32 "
        "{%0,%1,%2,%3},{%4,%5,%6,%7},{%8,%9},{%0,%1,%2,%3};"
        : "+f"(d[0]), "+f"(d[1]), "+f"(d[2]), "+f"(d[3])
        : "r"(a[0]), "r"(a[1]), "r"(a[2]), "r"(a[3]), "r"(b[0]), "r"(b[1]));
}
__device__ __forceinline__ void mma_bf16(float* d, const uint32_t* a, const uint32_t* b) {
    asm volatile(
        "mma.sync.aligned.m16n8k16.row.col.f32.bf16.bf16.f32 "
        "{%0,%1,%2,%3},{%4,%5,%6,%7},{%8,%9},{%0,%1,%2,%3};"
        : "+f"(d[0]), "+f"(d[1]), "+f"(d[2]), "+f"(d[3])
        : "r"(a[0]), "r"(a[1]), "r"(a[2]), "r"(a[3]), "r"(b[0]), "r"(b[1]));
}

// ---------------- cp.async ----------------
__device__ __forceinline__ uint32_t smem_u32(const void* p) {
    return (uint32_t)__cvta_generic_to_shared(p);
}
__device__ __forceinline__ void cpa16(uint32_t s, const void* g) {
    asm volatile("cp.async.cg.shared.global [%0], [%1], 16;" :: "r"(s), "l"(g));
}
#define CP_COMMIT asm volatile("cp.async.commit_group;")
#define CP_WAIT(n) asm volatile("cp.async.wait_group %0;" :: "n"(n))

// ---------------- fold kernels ----------------
// g_WextT[colp(C)][p] = dot(proj_w1[p,:], w_ih[C,:]) for C<1536, p<64; zero k<64 for C>=1536
__global__ void fold_wc_kernel(const float* __restrict__ w1, const float* __restrict__ wih) {
    __shared__ float As[64][64];
    __shared__ float Bs[64][65];
    int t = threadIdx.x;
    int n0 = blockIdx.x * 64;
    if (n0 >= 1536) {
        for (int i = t; i < 64 * 64; i += 256) {
            int p = i & 63, j = i >> 6;
            g_WextT[(size_t)colp(n0 + j) * KE + p] = __float2bfloat16(0.f);
        }
        return;
    }
    int nlane = t & 63;
    int pset = t >> 6;
    float acc[16];
#pragma unroll
    for (int i = 0; i < 16; ++i) acc[i] = 0.f;

    for (int kt = 0; kt < 512; kt += 64) {
        for (int i = t * 4; i < 64 * 64; i += 1024) {
            int p = i >> 6, c = i & 63;
            *(float4*)&As[p][c] = *(const float4*)(w1 + p * 512 + kt + c);
        }
        for (int i = t * 4; i < 64 * 64; i += 1024) {
            int r = i >> 6, c = i & 63;
            float4 v = *(const float4*)(wih + (size_t)(n0 + r) * 512 + kt + c);
            Bs[c + 0][r] = v.x; Bs[c + 1][r] = v.y; Bs[c + 2][r] = v.z; Bs[c + 3][r] = v.w;
        }
        __syncthreads();
#pragma unroll 8
        for (int k = 0; k < 64; ++k) {
            float bv = Bs[k][nlane];
#pragma unroll
            for (int pp = 0; pp < 16; ++pp)
                acc[pp] += As[pset * 16 + pp][k] * bv;
        }
        __syncthreads();
    }
    uint32_t* dst = (uint32_t*)(g_WextT + (size_t)colp(n0 + nlane) * KE + pset * 16);
#pragma unroll
    for (int pp = 0; pp < 8; ++pp) dst[pp] = packbf(acc[2 * pp], acc[2 * pp + 1]);
}

// g_WextT[colp(C)][64+k]: bf16 copy of whh rows (zero for i_n block)
__global__ __launch_bounds__(256) void fold_hh_kernel(const float* __restrict__ whh) {
    int w = (blockIdx.x * 256 + threadIdx.x) >> 5;  // C in [0,2048)
    int lane = threadIdx.x & 31;
    if (w >= NE) return;
    uint2* dst = (uint2*)(g_WextT + (size_t)colp(w) * KE + 64);
    if (w >= 1024 && w < 1536) {
        uint2 z = make_uint2(0u, 0u);
        for (int i = lane; i < 128; i += 32) dst[i] = z;
    } else {
        const float4* src = (const float4*)(whh + (size_t)((w < 1024) ? w : w - 512) * 512);
        for (int i = lane; i < 128; i += 32) {
            float4 v = src[i];
            dst[i] = make_uint2(packbf(v.x, v.y), packbf(v.z, v.w));
        }
    }
}

__global__ __launch_bounds__(256) void fold_bias_kernel(const float* __restrict__ wih,
                                                        const float* __restrict__ pb1,
                                                        const float* __restrict__ bih,
                                                        const float* __restrict__ bhh) {
    int C = (blockIdx.x * 256 + threadIdx.x) >> 5;
    int lane = threadIdx.x & 31;
    if (C >= NE) return;
    float v;
    if (C < 1536) {
        float s = 0.f;
        for (int h = lane; h < 512; h += 32) s += pb1[h] * wih[(size_t)C * 512 + h];
#pragma unroll
        for (int off = 16; off; off >>= 1) s += __shfl_xor_sync(0xFFFFFFFFu, s, off);
        float bc = bih[C] + s;
        v = (C < 1024) ? (bc + bhh[C]) : bc;
    } else {
        v = bhh[C - 512];
    }
    if (lane == 0) g_bias[colp(C)] = v;
}

// ---------------- hprev -> bf16 ----------------
__global__ __launch_bounds__(256) void conv_h_kernel(const float* __restrict__ hp) {
    int i = blockIdx.x * 256 + threadIdx.x;  // each handles 8 floats
    const float4* s = (const float4*)hp;
    float4 a = s[2 * i], b = s[2 * i + 1];
    uint4 o = make_uint4(packbf(a.x, a.y), packbf(a.z, a.w), packbf(b.x, b.y), packbf(b.z, b.w));
    ((uint4*)g_hprev_b)[i] = o;
}

// ---------------- GEMM1: hid = relu(obs @ w0 + b0), tf32, 3-stage, bf16 out ----------------
// stage layout: A (64x36 u32 = 9216B) | B (32x72 u32 = 9216B); 3 stages
#define G1_STAGE 18432
#define G1_SMEM (3 * G1_STAGE)  // 55296

__global__ __launch_bounds__(128) void gemm1_kernel(const float* __restrict__ obs,
                                                    const float* __restrict__ w0,
                                                    const float* __restrict__ b0) {
    extern __shared__ char smraw[];
    uint32_t sb = smem_u32(smraw);
    int t = threadIdx.x;
    int lane = t & 31, warp = t >> 5;
    int g = lane >> 2, c = lane & 3;
    int wm = warp >> 1, wn = warp & 1;
    int m0 = blockIdx.y * 64;

    float acc[2][4][4];
#pragma unroll
    for (int i = 0; i < 2; ++i)
#pragma unroll
        for (int j = 0; j < 4; ++j)
#pragma unroll
            for (int k = 0; k < 4; ++k) acc[i][j][k] = 0.f;

    int arow = t >> 3, ak4 = (t & 7) * 4;
    int bk = t >> 4, bn4 = (t & 15) * 4;

    auto load_tiles = [&](int kt, int buf) {
        uint32_t base = sb + buf * G1_STAGE;
#pragma unroll
        for (int p = 0; p < 4; ++p) {
            int row = p * 16 + arow;
            cpa16(base + (row * 36 + ak4) * 4, obs + (size_t)(m0 + row) * Gn + kt + ak4);
        }
#pragma unroll
        for (int p = 0; p < 4; ++p) {
            int k = p * 8 + bk;
            cpa16(base + 9216 + (k * 72 + bn4) * 4, w0 + (size_t)(kt + k) * 64 + bn4);
        }
    };

    const int NSTEP = Gn / 32;  // 64
    load_tiles(0, 0); CP_COMMIT;
    load_tiles(32, 1); CP_COMMIT;

    for (int i = 0; i < NSTEP; ++i) {
        if (i + 1 < NSTEP) { CP_WAIT(1); } else { CP_WAIT(0); }
        __syncthreads();
        if (i + 2 < NSTEP) { load_tiles((i + 2) * 32, (i + 2) % 3); CP_COMMIT; }
        const uint32_t* A = (const uint32_t*)(smraw + (i % 3) * G1_STAGE);
        const uint32_t* B = A + 2304;
#pragma unroll
        for (int kk = 0; kk < 4; ++kk) {
            uint32_t af[2][4], bf[4][2];
#pragma unroll
            for (int fm = 0; fm < 2; ++fm) {
                int r = wm * 32 + fm * 16;
                af[fm][0] = A[(r + g) * 36 + kk * 8 + c];
                af[fm][1] = A[(r + g + 8) * 36 + kk * 8 + c];
                af[fm][2] = A[(r + g) * 36 + kk * 8 + c + 4];
                af[fm][3] = A[(r + g + 8) * 36 + kk * 8 + c + 4];
            }
#pragma unroll
            for (int fn = 0; fn < 4; ++fn) {
                int cb = wn * 32 + fn * 8;
                bf[fn][0] = B[(kk * 8 + c) * 72 + cb + g];
                bf[fn][1] = B[(kk * 8 + c + 4) * 72 + cb + g];
            }
#pragma unroll
            for (int fm = 0; fm < 2; ++fm)
#pragma unroll
                for (int fn = 0; fn < 4; ++fn)
                    mma_tf32(acc[fm][fn], af[fm], bf[fn]);
        }
    }
    uint32_t* hb = (uint32_t*)g_hid;
#pragma unroll
    for (int fm = 0; fm < 2; ++fm) {
        int row = m0 + wm * 32 + fm * 16 + g;
#pragma unroll
        for (int fn = 0; fn < 4; ++fn) {
            int col = wn * 32 + fn * 8 + c * 2;
            float bA = b0[col], bB = b0[col + 1];
            hb[((size_t)row * PH + col) >> 1] =
                packbf(fmaxf(acc[fm][fn][0] + bA, 0.f), fmaxf(acc[fm][fn][1] + bB, 0.f));
            hb[((size_t)(row + 8) * PH + col) >> 1] =
                packbf(fmaxf(acc[fm][fn][2] + bA, 0.f), fmaxf(acc[fm][fn][3] + bB, 0.f));
        }
    }
}

// ---------------- GEMM2 bf16 + fused GRU gates, 3-stage ----------------
// stage layout: A (128x36 u32 = 18432B) | B (128x36 u32 = 18432B); 3 stages
// epilogue aliases stages 0-1 as [128][132] fp32 (67584B < 73728; final chunk is in stage 2)
#define G2_STAGE 36864
#define G2_SMEM (3 * G2_STAGE)  // 110592

__global__ __launch_bounds__(256) void gemm2_bf_kernel(const float* __restrict__ hprev,
                                                       float* __restrict__ hout) {
    extern __shared__ char smraw[];
    uint32_t sb = smem_u32(smraw);
    int t = threadIdx.x;
    int lane = t & 31, warp = t >> 5;
    int g = lane >> 2, cc4 = lane & 3;
    int wm = warp >> 2, wn = warp & 3;
    int m0 = blockIdx.y * 128;
    int n0 = blockIdx.x * 128;

    float acc[4][4][4];
#pragma unroll
    for (int i = 0; i < 4; ++i)
#pragma unroll
        for (int j = 0; j < 4; ++j)
#pragma unroll
            for (int k = 0; k < 4; ++k) acc[i][j][k] = 0.f;

    // chunk c: c==0 -> g_hid (k 0-63), c>=1 -> g_hprev_b
    auto load_chunk = [&](int c, int buf) {
        uint32_t base = sb + buf * G2_STAGE;
        const char* abase = (c == 0)
            ? (const char*)(g_hid + (size_t)m0 * PH)
            : (const char*)(g_hprev_b + (size_t)m0 * Hn + (c - 1) * 64);
        size_t apitch = (c == 0) ? (PH * 2) : (Hn * 2);
#pragma unroll
        for (int i = 0; i < 4; ++i) {
            int id = i * 256 + t;
            int r = id >> 3, s = id & 7;
            cpa16(base + r * 144 + s * 16, abase + (size_t)r * apitch + s * 16);
        }
        const char* bbase = (const char*)(g_WextT + (size_t)n0 * KE + c * 64);
#pragma unroll
        for (int i = 0; i < 4; ++i) {
            int id = i * 256 + t;
            int r = id >> 3, s = id & 7;
            cpa16(base + 18432 + r * 144 + s * 16, bbase + (size_t)r * (KE * 2) + s * 16);
        }
    };

    const int NC = KE / 64;  // 9
    load_chunk(0, 0); CP_COMMIT;
    load_chunk(1, 1); CP_COMMIT;

    for (int c = 0; c < NC; ++c) {
        if (c + 1 < NC) { CP_WAIT(1); } else { CP_WAIT(0); }
        __syncthreads();
        if (c + 2 < NC) { load_chunk(c + 2, (c + 2) % 3); CP_COMMIT; }
        const uint32_t* A = (const uint32_t*)(smraw + (c % 3) * G2_STAGE);
        const uint32_t* B = A + 4608;
#pragma unroll
        for (int ks = 0; ks < 4; ++ks) {
            uint32_t af[4][4], bf_[4][2];
#pragma unroll
            for (int fm = 0; fm < 4; ++fm) {
                int r = wm * 64 + fm * 16;
                af[fm][0] = A[(r + g) * 36 + ks * 8 + cc4];
                af[fm][1] = A[(r + g + 8) * 36 + ks * 8 + cc4];
                af[fm][2] = A[(r + g) * 36 + ks * 8 + cc4 + 4];
                af[fm][3] = A[(r + g + 8) * 36 + ks * 8 + cc4 + 4];
            }
#pragma unroll
            for (int fn = 0; fn < 4; ++fn) {
                int nr = wn * 32 + fn * 8 + g;
                bf_[fn][0] = B[nr * 36 + ks * 8 + cc4];
                bf_[fn][1] = B[nr * 36 + ks * 8 + cc4 + 4];
            }
#pragma unroll
            for (int fm = 0; fm < 4; ++fm)
#pragma unroll
                for (int fn = 0; fn < 4; ++fn)
                    mma_bf16(acc[fm][fn], af[fm], bf_[fn]);
        }
    }

    // ---- fused gate epilogue ----
    float* epi = (float*)smraw;  // [128][132], spans stages 0-1 only
#pragma unroll
    for (int fm = 0; fm < 4; ++fm) {
        int r0 = wm * 64 + fm * 16 + g;
#pragma unroll
        for (int fn = 0; fn < 4; ++fn) {
            int cw = wn * 32 + fn * 8 + 2 * cc4;
            epi[r0 * 132 + cw]           = acc[fm][fn][0];
            epi[r0 * 132 + cw + 1]       = acc[fm][fn][1];
            epi[(r0 + 8) * 132 + cw]     = acc[fm][fn][2];
            epi[(r0 + 8) * 132 + cw + 1] = acc[fm][fn][3];
        }
    }
    __syncthreads();
    int hbase = n0 >> 2;  // 32 h-columns per block
#pragma unroll
    for (int q = 0; q < 16; ++q) {
        int i = q * 256 + t;
        int row = i >> 5, jj = i & 31;
        float4 gq = *(float4*)&epi[row * 132 + 4 * jj];
        float4 bq = *(const float4*)(g_bias + n0 + 4 * jj);
        size_t idx = (size_t)(m0 + row) * Hn + hbase + jj;
        float hp = hprev[idx];
        float r = 1.f / (1.f + __expf(-(gq.x + bq.x)));
        float z = 1.f / (1.f + __expf(-(gq.y + bq.y)));
        float n = tanhf(gq.z + bq.z + r * (gq.w + bq.w));
        hout[idx] = (1.f - z) * n + z * hp;
    }
}

// ---------------- heads (one sample per warp) ----------------
__global__ __launch_bounds__(256) void heads_kernel(const float* __restrict__ h,
                                                    const int* __restrict__ aid,
                                                    const float* __restrict__ w1,
                                                    const float* __restrict__ b1,
                                                    const float* __restrict__ w2,
                                                    const float* __restrict__ b2,
                                                    float* __restrict__ out) {
    extern __shared__ float sm[];
    float* hs = sm;
    float* w1s = sm + 64 * Hn;
    __shared__ int s_aid[64];
    __shared__ int s_list[64];
    __shared__ int s_cnt;
    int t = threadIdx.x, lane = t & 31, warp = t >> 5;
    int b0 = blockIdx.x * 64;

    {
        const float4* src = (const float4*)(h + (size_t)b0 * Hn);
        float4* dst = (float4*)hs;
        for (int i = t; i < 64 * 128; i += 256) dst[i] = src[i];
    }
    if (t < 64) s_aid[t] = aid[b0 + t];
    __syncthreads();

    for (int a = 0; a < An; ++a) {
        if (t == 0) s_cnt = 0;
        __syncthreads();
        if (t < 64 && s_aid[t] == a) {
            int p = atomicAdd(&s_cnt, 1);
            s_list[p] = t;
        }
        __syncthreads();
        int cnt = s_cnt;
        if (cnt > 0) {
            const float4* wsrc = (const float4*)(w1 + (size_t)a * Hn * HH);
            float4* wdst = (float4*)w1s;
            for (int i = t; i < Hn * HH / 4; i += 256) wdst[i] = wsrc[i];
            __syncthreads();
            float w2v = w2[a * 32 + lane];
            float b1v = b1[a * 32 + lane];
            float b2v = b2[a];
            for (int s = warp; s < cnt; s += 8) {
                int l0 = s_list[s];
                const float4* r0 = (const float4*)(hs + l0 * Hn);
                float a0 = 0.f;
#pragma unroll 8
                for (int hq = 0; hq < 128; ++hq) {
                    float4 x0 = r0[hq];
                    a0 = fmaf(x0.x, w1s[(hq * 4 + 0) * 32 + lane], a0);
                    a0 = fmaf(x0.y, w1s[(hq * 4 + 1) * 32 + lane], a0);
                    a0 = fmaf(x0.z, w1s[(hq * 4 + 2) * 32 + lane], a0);
                    a0 = fmaf(x0.w, w1s[(hq * 4 + 3) * 32 + lane], a0);
                }
                float v0 = fmaxf(a0 + b1v, 0.f) * w2v;
#pragma unroll
                for (int off = 16; off; off >>= 1)
                    v0 += __shfl_xor_sync(0xFFFFFFFFu, v0, off);
                if (lane == 0) out[b0 + l0] = v0 + b2v;
            }
            __syncthreads();
        } else {
            __syncthreads();
        }
    }
}

// ---------------- launch ----------------
extern "C" void kernel_launch(void* const* d_in, const int* in_sizes, int n_in,
                              void* d_out, int out_size) {
    const float* obs   = (const float*)d_in[0];
    const float* hprev = (const float*)d_in[1];
    const int*   aid   = (const int*)d_in[2];
    const float* pw0   = (const float*)d_in[3];
    const float* pb0   = (const float*)d_in[4];
    const float* pw1   = (const float*)d_in[5];
    const float* pb1   = (const float*)d_in[6];
    const float* wih   = (const float*)d_in[7];
    const float* whh   = (const float*)d_in[8];
    const float* bih   = (const float*)d_in[9];
    const float* bhh   = (const float*)d_in[10];
    const float* hw1   = (const float*)d_in[11];
    const float* hb1   = (const float*)d_in[12];
    const float* hw2   = (const float*)d_in[13];
    const float* hb2   = (const float*)d_in[14];

    float* out  = (float*)d_out;
    float* hout = out + Bn;

    cudaFuncSetAttribute(heads_kernel, cudaFuncAttributeMaxDynamicSharedMemorySize, 196608);
    cudaFuncSetAttribute(gemm1_kernel, cudaFuncAttributeMaxDynamicSharedMemorySize, G1_SMEM);
    cudaFuncSetAttribute(gemm2_bf_kernel, cudaFuncAttributeMaxDynamicSharedMemorySize, G2_SMEM);

    fold_wc_kernel<<<NE / 64, 256>>>(pw1, wih);
    fold_hh_kernel<<<NE * 32 / 256, 256>>>(whh);
    fold_bias_kernel<<<NE * 32 / 256, 256>>>(wih, pb1, bih, bhh);
    conv_h_kernel<<<(Bn * Hn / 8) / 256, 256>>>(hprev);
    gemm1_kernel<<<dim3(1, Bn / 64), 128, G1_SMEM>>>(obs, pw0, pb0);
    gemm2_bf_kernel<<<dim3(NE / 128, Bn / 128), 256, G2_SMEM>>>(hprev, hout);
    heads_kernel<<<Bn / 64, 256, 196608>>>(hout, aid, hw1, hb1, hw2, hb2, out);
}

// round 17
// speedup vs baseline: 1.1345x; 1.1345x over previous
#include <cuda_runtime.h>
#include <cuda_bf16.h>
#include <cstdint>
#include <math.h>

#define Bn 32768
#define Gn 2048
#define Hn 512
#define An 8
#define PH 64
#define HH 32
#define KE 576      // 64 (hid) + 512 (h_prev)
#define NE 2048     // interleaved: col 4j+{0,1,2,3} = {r_sum, z_sum, i_n, h_n}

// ---------------- device scratch ----------------
__device__ __nv_bfloat16 g_WextT[(size_t)NE * KE];   // folded weight, [n][k] bf16
__device__ float g_bias[NE];                         // interleaved fp32
__device__ __nv_bfloat16 g_hid[(size_t)Bn * PH];     // gemm1 output, bf16
__device__ __nv_bfloat16 g_hprev_b[(size_t)Bn * Hn]; // bf16 copy of h_prev

__device__ __forceinline__ int colp(int C) { return 4 * (C & 511) + (C >> 9); }

__device__ __forceinline__ uint32_t packbf(float a, float b) {
    __nv_bfloat162 v = __float22bfloat162_rn(make_float2(a, b));
    return *(uint32_t*)&v;
}

// ---------------- mma ----------------
__device__ __forceinline__ void mma_tf32(float* d, const uint32_t* a, const uint32_t* b) {
    asm volatile(
        "mma.sync.aligned.m16n8k8.row.col.f32.tf32.tf32.f32 "
        "{%0,%1,%2,%3},{%4,%5,%6,%7},{%8,%9},{%0,%1,%2,%3};"
        : "+f"(d[0]), "+f"(d[1]), "+f"(d[2]), "+f"(d[3])
        : "r"(a[0]), "r"(a[1]), "r"(a[2]), "r"(a[3]), "r"(b[0]), "r"(b[1]));
}
__device__ __forceinline__ void mma_bf16(float* d, const uint32_t* a, const uint32_t* b) {
    asm volatile(
        "mma.sync.aligned.m16n8k16.row.col.f32.bf16.bf16.f32 "
        "{%0,%1,%2,%3},{%4,%5,%6,%7},{%8,%9},{%0,%1,%2,%3};"
        : "+f"(d[0]), "+f"(d[1]), "+f"(d[2]), "+f"(d[3])
        : "r"(a[0]), "r"(a[1]), "r"(a[2]), "r"(a[3]), "r"(b[0]), "r"(b[1]));
}

// ---------------- cp.async ----------------
__device__ __forceinline__ uint32_t smem_u32(const void* p) {
    return (uint32_t)__cvta_generic_to_shared(p);
}
__device__ __forceinline__ void cpa16(uint32_t s, const void* g) {
    asm volatile("cp.async.cg.shared.global [%0], [%1], 16;" :: "r"(s), "l"(g));
}
#define CP_COMMIT asm volatile("cp.async.commit_group;")
#define CP_WAIT(n) asm volatile("cp.async.wait_group %0;" :: "n"(n))

// ---------------- fold kernels ----------------
__global__ void fold_wc_kernel(const float* __restrict__ w1, const float* __restrict__ wih) {
    __shared__ float As[64][64];
    __shared__ float Bs[64][65];
    int t = threadIdx.x;
    int n0 = blockIdx.x * 64;
    if (n0 >= 1536) {
        for (int i = t; i < 64 * 64; i += 256) {
            int p = i & 63, j = i >> 6;
            g_WextT[(size_t)colp(n0 + j) * KE + p] = __float2bfloat16(0.f);
        }
        return;
    }
    int nlane = t & 63;
    int pset = t >> 6;
    float acc[16];
#pragma unroll
    for (int i = 0; i < 16; ++i) acc[i] = 0.f;

    for (int kt = 0; kt < 512; kt += 64) {
        for (int i = t * 4; i < 64 * 64; i += 1024) {
            int p = i >> 6, c = i & 63;
            *(float4*)&As[p][c] = *(const float4*)(w1 + p * 512 + kt + c);
        }
        for (int i = t * 4; i < 64 * 64; i += 1024) {
            int r = i >> 6, c = i & 63;
            float4 v = *(const float4*)(wih + (size_t)(n0 + r) * 512 + kt + c);
            Bs[c + 0][r] = v.x; Bs[c + 1][r] = v.y; Bs[c + 2][r] = v.z; Bs[c + 3][r] = v.w;
        }
        __syncthreads();
#pragma unroll 8
        for (int k = 0; k < 64; ++k) {
            float bv = Bs[k][nlane];
#pragma unroll
            for (int pp = 0; pp < 16; ++pp)
                acc[pp] += As[pset * 16 + pp][k] * bv;
        }
        __syncthreads();
    }
    uint32_t* dst = (uint32_t*)(g_WextT + (size_t)colp(n0 + nlane) * KE + pset * 16);
#pragma unroll
    for (int pp = 0; pp < 8; ++pp) dst[pp] = packbf(acc[2 * pp], acc[2 * pp + 1]);
}

__global__ __launch_bounds__(256) void fold_hh_kernel(const float* __restrict__ whh) {
    int w = (blockIdx.x * 256 + threadIdx.x) >> 5;
    int lane = threadIdx.x & 31;
    if (w >= NE) return;
    uint2* dst = (uint2*)(g_WextT + (size_t)colp(w) * KE + 64);
    if (w >= 1024 && w < 1536) {
        uint2 z = make_uint2(0u, 0u);
        for (int i = lane; i < 128; i += 32) dst[i] = z;
    } else {
        const float4* src = (const float4*)(whh + (size_t)((w < 1024) ? w : w - 512) * 512);
        for (int i = lane; i < 128; i += 32) {
            float4 v = src[i];
            dst[i] = make_uint2(packbf(v.x, v.y), packbf(v.z, v.w));
        }
    }
}

__global__ __launch_bounds__(256) void fold_bias_kernel(const float* __restrict__ wih,
                                                        const float* __restrict__ pb1,
                                                        const float* __restrict__ bih,
                                                        const float* __restrict__ bhh) {
    int C = (blockIdx.x * 256 + threadIdx.x) >> 5;
    int lane = threadIdx.x & 31;
    if (C >= NE) return;
    float v;
    if (C < 1536) {
        float s = 0.f;
        for (int h = lane; h < 512; h += 32) s += pb1[h] * wih[(size_t)C * 512 + h];
#pragma unroll
        for (int off = 16; off; off >>= 1) s += __shfl_xor_sync(0xFFFFFFFFu, s, off);
        float bc = bih[C] + s;
        v = (C < 1024) ? (bc + bhh[C]) : bc;
    } else {
        v = bhh[C - 512];
    }
    if (lane == 0) g_bias[colp(C)] = v;
}

// ---------------- hprev -> bf16 ----------------
__global__ __launch_bounds__(256) void conv_h_kernel(const float* __restrict__ hp) {
    int i = blockIdx.x * 256 + threadIdx.x;
    const float4* s = (const float4*)hp;
    float4 a = s[2 * i], b = s[2 * i + 1];
    uint4 o = make_uint4(packbf(a.x, a.y), packbf(a.z, a.w), packbf(b.x, b.y), packbf(b.z, b.w));
    ((uint4*)g_hprev_b)[i] = o;
}

// ---------------- GEMM1 (R12-validated: tf32, 2-stage static smem, bf16 out) ----------------
__global__ __launch_bounds__(128) void gemm1_kernel(const float* __restrict__ obs,
                                                    const float* __restrict__ w0,
                                                    const float* __restrict__ b0) {
    __shared__ uint32_t As[2][64][36];
    __shared__ uint32_t Bs[2][32][72];
    int t = threadIdx.x;
    int lane = t & 31, warp = t >> 5;
    int g = lane >> 2, c = lane & 3;
    int wm = warp >> 1, wn = warp & 1;
    int m0 = blockIdx.y * 64;

    float acc[2][4][4];
#pragma unroll
    for (int i = 0; i < 2; ++i)
#pragma unroll
        for (int j = 0; j < 4; ++j)
#pragma unroll
            for (int k = 0; k < 4; ++k) acc[i][j][k] = 0.f;

    int arow = t >> 3, ak4 = (t & 7) * 4;
    int bk = t >> 4, bn4 = (t & 15) * 4;

    auto load_tiles = [&](int kt, int buf) {
#pragma unroll
        for (int p = 0; p < 4; ++p) {
            int row = p * 16 + arow;
            cpa16(smem_u32(&As[buf][row][ak4]), obs + (size_t)(m0 + row) * Gn + kt + ak4);
        }
#pragma unroll
        for (int p = 0; p < 4; ++p) {
            int k = p * 8 + bk;
            cpa16(smem_u32(&Bs[buf][k][bn4]), w0 + (size_t)(kt + k) * 64 + bn4);
        }
    };

    const int NSTEP = Gn / 32;
    load_tiles(0, 0);
    CP_COMMIT;

    for (int i = 0; i < NSTEP; ++i) {
        if (i + 1 < NSTEP) {
            load_tiles((i + 1) * 32, (i + 1) & 1);
            CP_COMMIT;
            CP_WAIT(1);
        } else {
            CP_WAIT(0);
        }
        __syncthreads();
        int buf = i & 1;
#pragma unroll
        for (int kk = 0; kk < 4; ++kk) {
            uint32_t af[2][4], bf[4][2];
#pragma unroll
            for (int fm = 0; fm < 2; ++fm) {
                int r = wm * 32 + fm * 16;
                af[fm][0] = As[buf][r + g][kk * 8 + c];
                af[fm][1] = As[buf][r + g + 8][kk * 8 + c];
                af[fm][2] = As[buf][r + g][kk * 8 + c + 4];
                af[fm][3] = As[buf][r + g + 8][kk * 8 + c + 4];
            }
#pragma unroll
            for (int fn = 0; fn < 4; ++fn) {
                int cb = wn * 32 + fn * 8;
                bf[fn][0] = Bs[buf][kk * 8 + c][cb + g];
                bf[fn][1] = Bs[buf][kk * 8 + c + 4][cb + g];
            }
#pragma unroll
            for (int fm = 0; fm < 2; ++fm)
#pragma unroll
                for (int fn = 0; fn < 4; ++fn)
                    mma_tf32(acc[fm][fn], af[fm], bf[fn]);
        }
        __syncthreads();
    }
    uint32_t* hb = (uint32_t*)g_hid;
#pragma unroll
    for (int fm = 0; fm < 2; ++fm) {
        int row = m0 + wm * 32 + fm * 16 + g;
#pragma unroll
        for (int fn = 0; fn < 4; ++fn) {
            int col = wn * 32 + fn * 8 + c * 2;
            float bA = b0[col], bB = b0[col + 1];
            hb[((size_t)row * PH + col) >> 1] =
                packbf(fmaxf(acc[fm][fn][0] + bA, 0.f), fmaxf(acc[fm][fn][1] + bB, 0.f));
            hb[((size_t)(row + 8) * PH + col) >> 1] =
                packbf(fmaxf(acc[fm][fn][2] + bA, 0.f), fmaxf(acc[fm][fn][3] + bB, 0.f));
        }
    }
}

// ---------------- GEMM2 bf16 + fused GRU gates: 4-stage, K-chunk 32, 2 CTA/SM ----------------
// stage = A(128 rows x 80B) + B(128 rows x 80B) = 20480B; 4 stages = 81920B
// row pad 20 u32 (80B, 16B-aligned; banks g*20+c cover 0..31 -> conflict-free)
// epilogue aliases [128][132] fp32 (67584B); trailing __syncthreads before writes.
#define G2_PAD 20
#define G2_TILE 10240
#define G2_STAGE 20480
#define G2_SMEM (4 * G2_STAGE)  // 81920

__global__ __launch_bounds__(256) void gemm2_bf_kernel(const float* __restrict__ hprev,
                                                       float* __restrict__ hout) {
    extern __shared__ char smraw[];
    uint32_t sb = smem_u32(smraw);
    int t = threadIdx.x;
    int lane = t & 31, warp = t >> 5;
    int g = lane >> 2, cc4 = lane & 3;
    int wm = warp >> 2, wn = warp & 3;
    int m0 = blockIdx.y * 128;
    int n0 = blockIdx.x * 128;

    float acc[4][4][4];
#pragma unroll
    for (int i = 0; i < 4; ++i)
#pragma unroll
        for (int j = 0; j < 4; ++j)
#pragma unroll
            for (int k = 0; k < 4; ++k) acc[i][j][k] = 0.f;

    // chunk c covers k [c*32, c*32+32): c<2 from g_hid, else g_hprev_b
    auto load_chunk = [&](int c, int buf) {
        uint32_t base = sb + buf * G2_STAGE;
        const char* abase = (c < 2)
            ? (const char*)(g_hid + (size_t)m0 * PH + c * 32)
            : (const char*)(g_hprev_b + (size_t)m0 * Hn + (c - 2) * 32);
        size_t apitch = (c < 2) ? (PH * 2) : (Hn * 2);
#pragma unroll
        for (int i = 0; i < 2; ++i) {
            int id = i * 256 + t;
            int r = id >> 2, s = id & 3;
            cpa16(base + r * 80 + s * 16, abase + (size_t)r * apitch + s * 16);
        }
        const char* bbase = (const char*)(g_WextT + (size_t)n0 * KE + c * 32);
#pragma unroll
        for (int i = 0; i < 2; ++i) {
            int id = i * 256 + t;
            int r = id >> 2, s = id & 3;
            cpa16(base + G2_TILE + r * 80 + s * 16, bbase + (size_t)r * (KE * 2) + s * 16);
        }
    };

    const int NC = KE / 32;  // 18
    load_chunk(0, 0); CP_COMMIT;
    load_chunk(1, 1); CP_COMMIT;
    load_chunk(2, 2); CP_COMMIT;

    for (int c = 0; c < NC; ++c) {
        if (c + 1 == NC)      { CP_WAIT(0); }
        else if (c + 2 == NC) { CP_WAIT(1); }
        else                  { CP_WAIT(2); }
        __syncthreads();
        if (c + 3 < NC) { load_chunk(c + 3, (c + 3) & 3); CP_COMMIT; }
        const uint32_t* A = (const uint32_t*)(smraw + (c & 3) * G2_STAGE);
        const uint32_t* B = A + G2_TILE / 4;
#pragma unroll
        for (int ks = 0; ks < 2; ++ks) {
            uint32_t af[4][4], bf_[4][2];
#pragma unroll
            for (int fm = 0; fm < 4; ++fm) {
                int r = wm * 64 + fm * 16;
                af[fm][0] = A[(r + g) * G2_PAD + ks * 8 + cc4];
                af[fm][1] = A[(r + g + 8) * G2_PAD + ks * 8 + cc4];
                af[fm][2] = A[(r + g) * G2_PAD + ks * 8 + cc4 + 4];
                af[fm][3] = A[(r + g + 8) * G2_PAD + ks * 8 + cc4 + 4];
            }
#pragma unroll
            for (int fn = 0; fn < 4; ++fn) {
                int nr = wn * 32 + fn * 8 + g;
                bf_[fn][0] = B[nr * G2_PAD + ks * 8 + cc4];
                bf_[fn][1] = B[nr * G2_PAD + ks * 8 + cc4 + 4];
            }
#pragma unroll
            for (int fm = 0; fm < 4; ++fm)
#pragma unroll
                for (int fn = 0; fn < 4; ++fn)
                    mma_bf16(acc[fm][fn], af[fm], bf_[fn]);
        }
    }
    __syncthreads();  // all MMA smem reads done before epilogue aliases the stages

    // ---- fused gate epilogue (validated R6/R12) ----
    float* epi = (float*)smraw;  // [128][132]
#pragma unroll
    for (int fm = 0; fm < 4; ++fm) {
        int r0 = wm * 64 + fm * 16 + g;
#pragma unroll
        for (int fn = 0; fn < 4; ++fn) {
            int cw = wn * 32 + fn * 8 + 2 * cc4;
            epi[r0 * 132 + cw]           = acc[fm][fn][0];
            epi[r0 * 132 + cw + 1]       = acc[fm][fn][1];
            epi[(r0 + 8) * 132 + cw]     = acc[fm][fn][2];
            epi[(r0 + 8) * 132 + cw + 1] = acc[fm][fn][3];
        }
    }
    __syncthreads();
    int hbase = n0 >> 2;
#pragma unroll
    for (int q = 0; q < 16; ++q) {
        int i = q * 256 + t;
        int row = i >> 5, jj = i & 31;
        float4 gq = *(float4*)&epi[row * 132 + 4 * jj];
        float4 bq = *(const float4*)(g_bias + n0 + 4 * jj);
        size_t idx = (size_t)(m0 + row) * Hn + hbase + jj;
        float hp = hprev[idx];
        float r = 1.f / (1.f + __expf(-(gq.x + bq.x)));
        float z = 1.f / (1.f + __expf(-(gq.y + bq.y)));
        float n = tanhf(gq.z + bq.z + r * (gq.w + bq.w));
        hout[idx] = (1.f - z) * n + z * hp;
    }
}

// ---------------- heads (one sample per warp) ----------------
__global__ __launch_bounds__(256) void heads_kernel(const float* __restrict__ h,
                                                    const int* __restrict__ aid,
                                                    const float* __restrict__ w1,
                                                    const float* __restrict__ b1,
                                                    const float* __restrict__ w2,
                                                    const float* __restrict__ b2,
                                                    float* __restrict__ out) {
    extern __shared__ float sm[];
    float* hs = sm;
    float* w1s = sm + 64 * Hn;
    __shared__ int s_aid[64];
    __shared__ int s_list[64];
    __shared__ int s_cnt;
    int t = threadIdx.x, lane = t & 31, warp = t >> 5;
    int b0 = blockIdx.x * 64;

    {
        const float4* src = (const float4*)(h + (size_t)b0 * Hn);
        float4* dst = (float4*)hs;
        for (int i = t; i < 64 * 128; i += 256) dst[i] = src[i];
    }
    if (t < 64) s_aid[t] = aid[b0 + t];
    __syncthreads();

    for (int a = 0; a < An; ++a) {
        if (t == 0) s_cnt = 0;
        __syncthreads();
        if (t < 64 && s_aid[t] == a) {
            int p = atomicAdd(&s_cnt, 1);
            s_list[p] = t;
        }
        __syncthreads();
        int cnt = s_cnt;
        if (cnt > 0) {
            const float4* wsrc = (const float4*)(w1 + (size_t)a * Hn * HH);
            float4* wdst = (float4*)w1s;
            for (int i = t; i < Hn * HH / 4; i += 256) wdst[i] = wsrc[i];
            __syncthreads();
            float w2v = w2[a * 32 + lane];
            float b1v = b1[a * 32 + lane];
            float b2v = b2[a];
            for (int s = warp; s < cnt; s += 8) {
                int l0 = s_list[s];
                const float4* r0 = (const float4*)(hs + l0 * Hn);
                float a0 = 0.f;
#pragma unroll 8
                for (int hq = 0; hq < 128; ++hq) {
                    float4 x0 = r0[hq];
                    a0 = fmaf(x0.x, w1s[(hq * 4 + 0) * 32 + lane], a0);
                    a0 = fmaf(x0.y, w1s[(hq * 4 + 1) * 32 + lane], a0);
                    a0 = fmaf(x0.z, w1s[(hq * 4 + 2) * 32 + lane], a0);
                    a0 = fmaf(x0.w, w1s[(hq * 4 + 3) * 32 + lane], a0);
                }
                float v0 = fmaxf(a0 + b1v, 0.f) * w2v;
#pragma unroll
                for (int off = 16; off; off >>= 1)
                    v0 += __shfl_xor_sync(0xFFFFFFFFu, v0, off);
                if (lane == 0) out[b0 + l0] = v0 + b2v;
            }
            __syncthreads();
        } else {
            __syncthreads();
        }
    }
}

// ---------------- launch ----------------
extern "C" void kernel_launch(void* const* d_in, const int* in_sizes, int n_in,
                              void* d_out, int out_size) {
    const float* obs   = (const float*)d_in[0];
    const float* hprev = (const float*)d_in[1];
    const int*   aid   = (const int*)d_in[2];
    const float* pw0   = (const float*)d_in[3];
    const float* pb0   = (const float*)d_in[4];
    const float* pw1   = (const float*)d_in[5];
    const float* pb1   = (const float*)d_in[6];
    const float* wih   = (const float*)d_in[7];
    const float* whh   = (const float*)d_in[8];
    const float* bih   = (const float*)d_in[9];
    const float* bhh   = (const float*)d_in[10];
    const float* hw1   = (const float*)d_in[11];
    const float* hb1   = (const float*)d_in[12];
    const float* hw2   = (const float*)d_in[13];
    const float* hb2   = (const float*)d_in[14];

    float* out  = (float*)d_out;
    float* hout = out + Bn;

    cudaFuncSetAttribute(heads_kernel, cudaFuncAttributeMaxDynamicSharedMemorySize, 196608);
    cudaFuncSetAttribute(gemm2_bf_kernel, cudaFuncAttributeMaxDynamicSharedMemorySize, G2_SMEM);

    fold_wc_kernel<<<NE / 64, 256>>>(pw1, wih);
    fold_hh_kernel<<<NE * 32 / 256, 256>>>(whh);
    fold_bias_kernel<<<NE * 32 / 256, 256>>>(wih, pb1, bih, bhh);
    conv_h_kernel<<<(Bn * Hn / 8) / 256, 256>>>(hprev);
    gemm1_kernel<<<dim3(1, Bn / 64), 128>>>(obs, pw0, pb0);
    gemm2_bf_kernel<<<dim3(NE / 128, Bn / 128), 256, G2_SMEM>>>(hprev, hout);
    heads_kernel<<<Bn / 64, 256, 196608>>>(hout, aid, hw1, hb1, hw2, hb2, out);
}